// round 9
// baseline (speedup 1.0000x reference)
#include <cuda_runtime.h>
#include <cuda_bf16.h>
#include <cstdint>

// ComboSumModule: 6 tensors (N=2048, M_i, K_i) fp32, sum over axis 1.
//   x0:(2048,128,64) x1:(2048,32,32) x2:(2048,64,64)
//   x3:(2048,16,48)  x4:(2048,200,32) x5:(2048,8,8)
// Output float offsets: 0, 131072, 196608, 327680, 425984, 491520.
//
// R9: persistent grid (888 blocks = 148 SM x 6) looping over 5488 virtual
// work units; per-unit structure identical to R8 (warp-sequential 512B
// bursts + block-local smem combine, single launch, no atomics).

__device__ __forceinline__ void f4_acc(float4& a, const float4 v) {
    a.x += v.x; a.y += v.y; a.z += v.z; a.w += v.w;
}

// F4N: float4 per n. Kv: K/4. NPB: n per unit. NW: warps per n (NPB*NW==8).
// CF4: float4 per chunk. ITERS: ceil(CF4/32). TAIL: lanes active in last iter.
template<int F4N, int Kv, int NPB, int NW, int CF4, int ITERS, int TAIL>
__device__ __forceinline__ void seg_block(const float* __restrict__ in,
                                          float* __restrict__ out,
                                          int unit, int tid,
                                          float4 (*part)[16]) {
    const float4* __restrict__ in4 = reinterpret_cast<const float4*>(in);
    float4* __restrict__ out4 = reinterpret_cast<float4*>(out);
    const int w    = tid >> 5;
    const int lane = tid & 31;
    const int n_l  = w / NW;
    const int c    = w % NW;
    const int n    = unit * NPB + n_l;

    const float4* __restrict__ p = in4 + (size_t)n * F4N + c * CF4 + lane;

    float4 a0 = make_float4(0.f, 0.f, 0.f, 0.f);
    float4 a1 = make_float4(0.f, 0.f, 0.f, 0.f);
    #pragma unroll
    for (int i = 0; i < ITERS; ++i) {
        if (TAIL == 32 || i + 1 < ITERS || lane < TAIL) {
            float4 v = __ldcs(p + i * 32);      // warp: 512B contiguous
            if (i & 1) f4_acc(a1, v); else f4_acc(a0, v);
        }
    }
    float4 s;
    s.x = a0.x + a1.x; s.y = a0.y + a1.y;
    s.z = a0.z + a1.z; s.w = a0.w + a1.w;

    #pragma unroll
    for (int d = Kv; d < 32; d <<= 1) {
        s.x += __shfl_xor_sync(0xFFFFFFFFu, s.x, d);
        s.y += __shfl_xor_sync(0xFFFFFFFFu, s.y, d);
        s.z += __shfl_xor_sync(0xFFFFFFFFu, s.z, d);
        s.w += __shfl_xor_sync(0xFFFFFFFFu, s.w, d);
    }

    if (NW == 1) {
        if (lane < Kv) out4[(size_t)n * Kv + lane] = s;
    } else {
        if (lane < Kv) part[w][lane] = s;
        __syncthreads();
        if (tid < NPB * Kv) {                   // NPB*Kv <= 32
            const int nl = tid / Kv;
            const int k  = tid % Kv;
            float4 t = part[nl * NW][k];
            #pragma unroll
            for (int ww = 1; ww < NW; ++ww)
                f4_acc(t, part[nl * NW + ww][k]);
            out4[(size_t)(unit * NPB + nl) * Kv + k] = t;
        }
    }
}

// Per-thread style for Kv not dividing 32 / tiny segments.
template<int M, int Kv, int C>
__device__ __forceinline__ void seg_thread(const float* __restrict__ in,
                                           float* __restrict__ out, int t) {
    const float4* __restrict__ in4 = reinterpret_cast<const float4*>(in);
    float4* __restrict__ out4 = reinterpret_cast<float4*>(out);
    const int k = t % Kv;
    const int n = t / Kv;
    const float4* __restrict__ p = in4 + (size_t)n * (size_t)(M * Kv) + k;
    float4 a0 = make_float4(0.f, 0.f, 0.f, 0.f);
    float4 a1 = make_float4(0.f, 0.f, 0.f, 0.f);
    #pragma unroll
    for (int m = 0; m < C; ++m) {
        float4 v = __ldcs(p + (size_t)m * Kv);
        if (m & 1) f4_acc(a1, v); else f4_acc(a0, v);
    }
    float4 s;
    s.x = a0.x + a1.x; s.y = a0.y + a1.y;
    s.z = a0.z + a1.z; s.w = a0.w + a1.w;
    out4[(size_t)n * Kv + k] = s;
}

// Virtual unit layout (heavy first):
//  seg3: [0, 96)        thread-style 64KB
//  seg0: [96, 2144)     NPB=1 NW=8 CF4=256 ITERS=8          32KB
//  seg2: [2144, 3168)   NPB=2 NW=4 CF4=256 ITERS=8          32KB
//  seg1: [3168, 3424)   NPB=8 NW=1 CF4=256 ITERS=8          32KB
//  seg4: [3424, 5472)   NPB=1 NW=8 CF4=200 ITERS=7 TAIL=8   25.6KB
//  seg5: [5472, 5488)   thread-style
static constexpr int TOTAL_UNITS = 5488;
static constexpr int GRID_BLOCKS = 148 * 6;   // persistent

__device__ __forceinline__
void do_unit(int u, int tid,
             const float* __restrict__ x0, const float* __restrict__ x1,
             const float* __restrict__ x2, const float* __restrict__ x3,
             const float* __restrict__ x4, const float* __restrict__ x5,
             float* __restrict__ out, float4 (*part)[16]) {
    if (u < 96) {
        seg_thread<16, 12, 16>(x3, out + 327680, u * 256 + tid);
    } else if (u < 2144) {
        seg_block<2048, 16, 1, 8, 256, 8, 32>(x0, out + 0,      u - 96,   tid, part);
    } else if (u < 3168) {
        seg_block<1024, 16, 2, 4, 256, 8, 32>(x2, out + 196608, u - 2144, tid, part);
    } else if (u < 3424) {
        seg_block<256,  8,  8, 1, 256, 8, 32>(x1, out + 131072, u - 3168, tid, part);
    } else if (u < 5472) {
        seg_block<1600, 8,  1, 8, 200, 7, 8 >(x4, out + 425984, u - 3424, tid, part);
    } else {
        seg_thread<8, 2, 8>(x5, out + 491520, (u - 5472) * 256 + tid);
    }
}

__global__ __launch_bounds__(256, 6)
void combo_sum_kernel(const float* __restrict__ x0, const float* __restrict__ x1,
                      const float* __restrict__ x2, const float* __restrict__ x3,
                      const float* __restrict__ x4, const float* __restrict__ x5,
                      float* __restrict__ out) {
    __shared__ float4 part[8][16];
    const int tid = threadIdx.x;

    for (int u = blockIdx.x; u < TOTAL_UNITS; u += GRID_BLOCKS) {
        if (u != (int)blockIdx.x)
            __syncthreads();   // guard smem reuse across unit iterations
        do_unit(u, tid, x0, x1, x2, x3, x4, x5, out, part);
    }
}

extern "C" void kernel_launch(void* const* d_in, const int* in_sizes, int n_in,
                              void* d_out, int out_size) {
    const float* x0 = (const float*)d_in[0];
    const float* x1 = (const float*)d_in[1];
    const float* x2 = (const float*)d_in[2];
    const float* x3 = (const float*)d_in[3];
    const float* x4 = (const float*)d_in[4];
    const float* x5 = (const float*)d_in[5];
    float* out = (float*)d_out;

    combo_sum_kernel<<<GRID_BLOCKS, 256>>>(x0, x1, x2, x3, x4, x5, out);
}

// round 10
// speedup vs baseline: 1.1304x; 1.1304x over previous
#include <cuda_runtime.h>
#include <cuda_bf16.h>
#include <cstdint>

// ComboSumModule: 6 tensors (N=2048, M_i, K_i) fp32, sum over axis 1.
//   x0:(2048,128,64) x1:(2048,32,32) x2:(2048,64,64)
//   x3:(2048,16,48)  x4:(2048,200,32) x5:(2048,8,8)
// Output float offsets: 0, 131072, 196608, 327680, 425984, 491520.
//
// R10: R8 structure (block-per-unit, warp-sequential 512B bursts, smem
// combine, single launch) + occupancy ceiling 7 blocks/SM (regs<=36) and
// explicit tail handling for seg4 (no per-iteration predicate).

__device__ __forceinline__ void f4_acc(float4& a, const float4 v) {
    a.x += v.x; a.y += v.y; a.z += v.z; a.w += v.w;
}

// F4N: float4 per n. Kv: K/4. NPB: n per block. NW: warps per n (NPB*NW==8).
// CF4: float4 per chunk. FITERS: full 32-lane iters. TAIL: extra lanes after
// the full iters (CF4 = FITERS*32 + TAIL).
template<int F4N, int Kv, int NPB, int NW, int CF4, int FITERS, int TAIL>
__device__ __forceinline__ void seg_block(const float* __restrict__ in,
                                          float* __restrict__ out,
                                          int blk, int tid,
                                          float4 (*part)[16]) {
    const float4* __restrict__ in4 = reinterpret_cast<const float4*>(in);
    float4* __restrict__ out4 = reinterpret_cast<float4*>(out);
    const int w    = tid >> 5;
    const int lane = tid & 31;
    const int n_l  = w / NW;
    const int c    = w % NW;
    const int n    = blk * NPB + n_l;

    const float4* __restrict__ p = in4 + (size_t)n * F4N + c * CF4 + lane;

    float4 a0 = make_float4(0.f, 0.f, 0.f, 0.f);
    float4 a1 = make_float4(0.f, 0.f, 0.f, 0.f);
    #pragma unroll
    for (int i = 0; i < FITERS; ++i) {
        float4 v = __ldcs(p + i * 32);          // warp: 512B contiguous
        if (i & 1) f4_acc(a1, v); else f4_acc(a0, v);
    }
    if (TAIL > 0) {
        if (lane < TAIL) {
            float4 v = __ldcs(p + FITERS * 32);
            f4_acc(a0, v);
        }
    }
    float4 s;
    s.x = a0.x + a1.x; s.y = a0.y + a1.y;
    s.z = a0.z + a1.z; s.w = a0.w + a1.w;

    // In-warp: fold the 32/Kv row-phases (lanes equal mod Kv).
    #pragma unroll
    for (int d = Kv; d < 32; d <<= 1) {
        s.x += __shfl_xor_sync(0xFFFFFFFFu, s.x, d);
        s.y += __shfl_xor_sync(0xFFFFFFFFu, s.y, d);
        s.z += __shfl_xor_sync(0xFFFFFFFFu, s.z, d);
        s.w += __shfl_xor_sync(0xFFFFFFFFu, s.w, d);
    }

    if (NW == 1) {
        if (lane < Kv) out4[(size_t)n * Kv + lane] = s;
    } else {
        if (lane < Kv) part[w][lane] = s;
        __syncthreads();
        if (tid < NPB * Kv) {                   // NPB*Kv <= 32
            const int nl = tid / Kv;
            const int k  = tid % Kv;
            float4 t = part[nl * NW][k];
            #pragma unroll
            for (int ww = 1; ww < NW; ++ww)
                f4_acc(t, part[nl * NW + ww][k]);
            out4[(size_t)(blk * NPB + nl) * Kv + k] = t;
        }
    }
}

// Per-thread style for Kv not dividing 32 / tiny segments.
template<int M, int Kv, int C>
__device__ __forceinline__ void seg_thread(const float* __restrict__ in,
                                           float* __restrict__ out, int t) {
    const float4* __restrict__ in4 = reinterpret_cast<const float4*>(in);
    float4* __restrict__ out4 = reinterpret_cast<float4*>(out);
    const int k = t % Kv;
    const int n = t / Kv;
    const float4* __restrict__ p = in4 + (size_t)n * (size_t)(M * Kv) + k;
    float4 a0 = make_float4(0.f, 0.f, 0.f, 0.f);
    float4 a1 = make_float4(0.f, 0.f, 0.f, 0.f);
    #pragma unroll
    for (int m = 0; m < C; ++m) {
        float4 v = __ldcs(p + (size_t)m * Kv);
        if (m & 1) f4_acc(a1, v); else f4_acc(a0, v);
    }
    float4 s;
    s.x = a0.x + a1.x; s.y = a0.y + a1.y;
    s.z = a0.z + a1.z; s.w = a0.w + a1.w;
    out4[(size_t)n * Kv + k] = s;
}

// Block layout (heavy blocks first for tail balance):
//  seg3: [0, 96)        thread-style, 64KB/block
//  seg0: [96, 2144)     NPB=1 NW=8 CF4=256 FITERS=8          32KB/block
//  seg2: [2144, 3168)   NPB=2 NW=4 CF4=256 FITERS=8          32KB/block
//  seg1: [3168, 3424)   NPB=8 NW=1 CF4=256 FITERS=8          32KB/block
//  seg4: [3424, 5472)   NPB=1 NW=8 CF4=200 FITERS=6 TAIL=8   25.6KB/block
//  seg5: [5472, 5488)   thread-style
static constexpr int TOTAL_BLOCKS = 5488;

__global__ __launch_bounds__(256, 7)
void combo_sum_kernel(const float* __restrict__ x0, const float* __restrict__ x1,
                      const float* __restrict__ x2, const float* __restrict__ x3,
                      const float* __restrict__ x4, const float* __restrict__ x5,
                      float* __restrict__ out) {
    __shared__ float4 part[8][16];
    const int blk = blockIdx.x;
    const int tid = threadIdx.x;

    if (blk < 96) {
        seg_thread<16, 12, 16>(x3, out + 327680, blk * 256 + tid);
    } else if (blk < 2144) {
        seg_block<2048, 16, 1, 8, 256, 8, 0>(x0, out + 0,      blk - 96,   tid, part);
    } else if (blk < 3168) {
        seg_block<1024, 16, 2, 4, 256, 8, 0>(x2, out + 196608, blk - 2144, tid, part);
    } else if (blk < 3424) {
        seg_block<256,  8,  8, 1, 256, 8, 0>(x1, out + 131072, blk - 3168, tid, part);
    } else if (blk < 5472) {
        seg_block<1600, 8,  1, 8, 200, 6, 8>(x4, out + 425984, blk - 3424, tid, part);
    } else {
        seg_thread<8, 2, 8>(x5, out + 491520, (blk - 5472) * 256 + tid);
    }
}

extern "C" void kernel_launch(void* const* d_in, const int* in_sizes, int n_in,
                              void* d_out, int out_size) {
    const float* x0 = (const float*)d_in[0];
    const float* x1 = (const float*)d_in[1];
    const float* x2 = (const float*)d_in[2];
    const float* x3 = (const float*)d_in[3];
    const float* x4 = (const float*)d_in[4];
    const float* x5 = (const float*)d_in[5];
    float* out = (float*)d_out;

    combo_sum_kernel<<<TOTAL_BLOCKS, 256>>>(x0, x1, x2, x3, x4, x5, out);
}